// round 7
// baseline (speedup 1.0000x reference)
#include <cuda_runtime.h>
#include <cuda_bf16.h>
#include <stdint.h>

// ---------------------------------------------------------------------------
// GCN layer: out = scatter_sum(y[src] -> dst) + bias, where y = x @ W^T
// Inputs (int64 tensors arrive as int32 per harness dtype mapping):
//   0: x float32 [N,64]  1: W float32 [64,64]  2: bias float32 [64]
//   3: edge_index int32 [2,E]  4..6: unused hints
// Output: float32 [N, 64]
//
// Pipeline:
//   1) zero_deg        : reset CSR degree counters + overflow counter (tiny)
//   2) fused_gemm_build: block roles INTERLEAVED (1 gemm : 4 build) so the
//                        FMA-bound GEMM and L2-bound CSR build co-reside in
//                        every wave. GEMM uses packed fma.rn.f32x2 (2 FMA per
//                        FMA-pipe instruction) with row-pairs pre-packed in
//                        shared memory.
//   3) gather_csr      : per-dst accumulate from L2-resident y (+bias),
//                        single overwrite, no atomics; overflow fixup folded
//                        in (normally zero work).
// ---------------------------------------------------------------------------

#define D 64
#define MAX_N 100000
#define CAP 64
#define OVF_MAX 8192

typedef unsigned long long ull;

__device__ __align__(16) float g_y[(size_t)MAX_N * D];
__device__ int g_deg[MAX_N];
__device__ int g_adj[(size_t)MAX_N * CAP];
__device__ int g_ovf_cnt;
__device__ int g_ovf[OVF_MAX];

__device__ __forceinline__ ull pack2(float v) {
    ull d;
    asm("mov.b64 %0, {%1, %1};" : "=l"(d) : "f"(v));
    return d;
}
__device__ __forceinline__ ull packab(float a, float b) {
    ull d;
    asm("mov.b64 %0, {%1, %2};" : "=l"(d) : "f"(a), "f"(b));
    return d;
}
__device__ __forceinline__ ull fma2(ull a, ull b, ull c) {
    ull d;
    asm("fma.rn.f32x2 %0, %1, %2, %3;" : "=l"(d) : "l"(a), "l"(b), "l"(c));
    return d;
}
__device__ __forceinline__ float lo32(ull a) { return __uint_as_float((unsigned)a); }
__device__ __forceinline__ float hi32(ull a) { return __uint_as_float((unsigned)(a >> 32)); }

// ---------------------------------------------------------------------------
// Kernel 1: reset degree counters + overflow count
// ---------------------------------------------------------------------------
__global__ __launch_bounds__(256) void zero_deg(int N)
{
    int i = blockIdx.x * 256 + threadIdx.x;
    if (i < N) g_deg[i] = 0;
    if (i == 0) g_ovf_cnt = 0;
}

// ---------------------------------------------------------------------------
// Kernel 2: fused GEMM + CSR build, interleaved roles.
//   blockIdx % 5 == 0 (and tile in range) -> GEMM tile (64 rows)
//   otherwise                             -> 256 edges -> CSR slots
// ---------------------------------------------------------------------------
__global__ __launch_bounds__(256) void fused_gemm_build(
    const float* __restrict__ x, const float* __restrict__ W,
    float* __restrict__ y, int N,
    const int* __restrict__ ei, int E, int gemmBlocks)
{
    const int tid = threadIdx.x;
    const int b = blockIdx.x;
    const int g = b / 5;
    const int rem = b - g * 5;
    const bool isGemm = (rem == 0) && (g < gemmBlocks);

    // static smem (allocated for all blocks; build blocks ignore it)
    __shared__ float sWt[D][D + 4];       // sWt[k][o] = W[o][k]
    __shared__ ull   sxp[D][33];          // sxp[k][p] = pack(x[p][k], x[p+32][k])

    if (!isGemm) {
        // ----- CSR build branch -----
        int nGemmBefore = g + (rem > 0 ? 1 : 0);
        if (nGemmBefore > gemmBlocks) nGemmBefore = gemmBlocks;
        int buildIdx = b - nGemmBefore;
        int e = buildIdx * 256 + tid;
        if (e >= E) return;
        int src = __ldg(&ei[e]);
        int dst = __ldg(&ei[E + e]);
        if (((unsigned)src >= (unsigned)N) | ((unsigned)dst >= (unsigned)N)) return;
        int pos = atomicAdd(&g_deg[dst], 1);
        if (pos < CAP) {
            g_adj[(size_t)dst * CAP + pos] = src;
        } else {
            int i = atomicAdd(&g_ovf_cnt, 1);
            if (i < OVF_MAX) g_ovf[i] = e;
        }
        return;
    }

    // ----- GEMM branch: y = x @ W^T for rows [row0, row0+64) -----
    const int row0 = g * 64;

    // W -> smem transposed
    #pragma unroll
    for (int i = tid; i < D * D; i += 256)
        sWt[i & 63][i >> 6] = W[i];

    // x tile -> smem as packed row-pairs (p, p+32), k-major.
    // 512 (p,c4) slots over 2 iterations; each slot packs 4 k-values.
    #pragma unroll
    for (int it = 0; it < 2; it++) {
        int j = tid + it * 256;            // 0..511
        int p  = j >> 4;                   // 0..31
        int c4 = j & 15;                   // float4 index (k = 4*c4+e)
        int ra = row0 + p, rb = row0 + p + 32;
        float4 va = make_float4(0.f, 0.f, 0.f, 0.f);
        float4 vb = va;
        if (ra < N) va = reinterpret_cast<const float4*>(x)[(size_t)ra * 16 + c4];
        if (rb < N) vb = reinterpret_cast<const float4*>(x)[(size_t)rb * 16 + c4];
        int k = c4 * 4;
        sxp[k + 0][p] = packab(va.x, vb.x);
        sxp[k + 1][p] = packab(va.y, vb.y);
        sxp[k + 2][p] = packab(va.z, vb.z);
        sxp[k + 3][p] = packab(va.w, vb.w);
    }
    __syncthreads();

    const int tx = tid & 15;               // col group (4 cols)
    const int ty = tid >> 4;               // 0..15

    // Packed accumulators: A* = rows (ty, ty+32), B* = rows (ty+16, ty+48)
    ull A0 = 0, A1 = 0, A2 = 0, A3 = 0;
    ull B0 = 0, B1 = 0, B2 = 0, B3 = 0;

    #pragma unroll 8
    for (int k = 0; k < D; k++) {
        float4 w = *reinterpret_cast<const float4*>(&sWt[k][tx * 4]);
        ull wx = pack2(w.x), wy = pack2(w.y), wz = pack2(w.z), ww = pack2(w.w);
        ull xA = sxp[k][ty];
        ull xB = sxp[k][ty + 16];
        A0 = fma2(xA, wx, A0); A1 = fma2(xA, wy, A1);
        A2 = fma2(xA, wz, A2); A3 = fma2(xA, ww, A3);
        B0 = fma2(xB, wx, B0); B1 = fma2(xB, wy, B1);
        B2 = fma2(xB, wz, B2); B3 = fma2(xB, ww, B3);
    }

    float4* y4 = reinterpret_cast<float4*>(y);
    int r0 = row0 + ty;
    if (r0 < N)
        y4[(size_t)r0 * 16 + tx] = make_float4(lo32(A0), lo32(A1), lo32(A2), lo32(A3));
    if (r0 + 16 < N)
        y4[(size_t)(r0 + 16) * 16 + tx] = make_float4(lo32(B0), lo32(B1), lo32(B2), lo32(B3));
    if (r0 + 32 < N)
        y4[(size_t)(r0 + 32) * 16 + tx] = make_float4(hi32(A0), hi32(A1), hi32(A2), hi32(A3));
    if (r0 + 48 < N)
        y4[(size_t)(r0 + 48) * 16 + tx] = make_float4(hi32(B0), hi32(B1), hi32(B2), hi32(B3));
}

// ---------------------------------------------------------------------------
// Kernel 3: gather. 16 threads per dst (thread c owns float4 chunk c).
// Single write per output row, bias folded in, no atomics. Overflow fixup
// folded in (g_ovf_cnt is normally 0 -> one broadcast load).
// ---------------------------------------------------------------------------
__global__ __launch_bounds__(256) void gather_csr(
    const float* __restrict__ bias, float* __restrict__ out, int N,
    const int* __restrict__ ei, int E)
{
    int d = blockIdx.x * 16 + (threadIdx.x >> 4);
    int c = threadIdx.x & 15;
    if (d >= N) return;

    int cnt = g_deg[d];
    if (cnt > CAP) cnt = CAP;

    float4 acc = __ldg(reinterpret_cast<const float4*>(bias) + c);
    const int* lst = &g_adj[(size_t)d * CAP];
    const float4* y4 = reinterpret_cast<const float4*>(g_y);

    float4 acc2 = make_float4(0.f, 0.f, 0.f, 0.f);
    int i = 0;
    for (; i + 2 <= cnt; i += 2) {
        int s0 = __ldg(&lst[i]);
        int s1 = __ldg(&lst[i + 1]);
        float4 v0 = __ldg(y4 + (size_t)s0 * 16 + c);
        float4 v1 = __ldg(y4 + (size_t)s1 * 16 + c);
        acc.x  += v0.x; acc.y  += v0.y; acc.z  += v0.z; acc.w  += v0.w;
        acc2.x += v1.x; acc2.y += v1.y; acc2.z += v1.z; acc2.w += v1.w;
    }
    if (i < cnt) {
        int s0 = __ldg(&lst[i]);
        float4 v0 = __ldg(y4 + (size_t)s0 * 16 + c);
        acc.x += v0.x; acc.y += v0.y; acc.z += v0.z; acc.w += v0.w;
    }
    acc.x += acc2.x; acc.y += acc2.y; acc.z += acc2.z; acc.w += acc2.w;

    // Overflow fixup (statistically dead: deg>CAP ~ never for Poisson(16))
    int ovf = g_ovf_cnt;
    if (ovf > 0) {
        if (ovf > OVF_MAX) ovf = OVF_MAX;
        for (int j = 0; j < ovf; j++) {
            int e = g_ovf[j];
            if (__ldg(&ei[E + e]) != d) continue;
            int s = __ldg(&ei[e]);
            float4 v = __ldg(y4 + (size_t)s * 16 + c);
            acc.x += v.x; acc.y += v.y; acc.z += v.z; acc.w += v.w;
        }
    }

    reinterpret_cast<float4*>(out)[(size_t)d * 16 + c] = acc;
}

// ---------------------------------------------------------------------------
extern "C" void kernel_launch(void* const* d_in, const int* in_sizes, int n_in,
                              void* d_out, int out_size)
{
    const float* x    = (const float*)d_in[0];
    const float* W    = (const float*)d_in[1];
    const float* bias = (const float*)d_in[2];
    const int*   ei   = (const int*)d_in[3];

    const int N = in_sizes[0] / D;
    const int E = in_sizes[3] / 2;
    float* out = (float*)d_out;

    float* y;
    cudaGetSymbolAddress((void**)&y, g_y);

    const int gemmBlocks = (N + 63) / 64;
    int buildBlocks = gemmBlocks * 4;                 // 1:4 interleave ratio
    const int needed = (E + 255) / 256;
    if (buildBlocks < needed) buildBlocks = needed;   // coverage guarantee
    const int total = gemmBlocks + buildBlocks;

    zero_deg<<<(N + 255) / 256, 256>>>(N);
    fused_gemm_build<<<total, 256>>>(x, W, y, N, ei, E, gemmBlocks);
    gather_csr<<<(N + 15) / 16, 256>>>(bias, out, N, ei, E);
}

// round 8
// speedup vs baseline: 1.0726x; 1.0726x over previous
#include <cuda_runtime.h>
#include <cuda_bf16.h>
#include <stdint.h>

// ---------------------------------------------------------------------------
// GCN layer: out = scatter_sum(y[src] -> dst) + bias, where y = x @ W^T
// Inputs (int64 tensors arrive as int32 per harness dtype mapping):
//   0: x float32 [N,64]  1: W float32 [64,64]  2: bias float32 [64]
//   3: edge_index int32 [2,E]  4..6: unused hints
// Output: float32 [N, 64]
//
// Pipeline:
//   1) cudaMemsetAsync : reset CSR degree counters + overflow counter
//   2) fused_gemm_build: blocks [0,Gg) = GEMM tiles (f32x2 packed FMA,
//                        column-paired accumulators, NO smem repack);
//                        blocks [Gg,..) = CSR build (edge -> dst slot).
//   3) gather_csr      : per-dst accumulate from L2-resident y (+bias),
//                        no atomics; overflow fixup folded in (normally 0).
// ---------------------------------------------------------------------------

#define D 64
#define MAX_N 100000
#define CAP 64
#define OVF_MAX 8192

typedef unsigned long long ull;

__device__ __align__(16) float g_y[(size_t)MAX_N * D];
__device__ int g_deg[MAX_N];
__device__ int g_adj[(size_t)MAX_N * CAP];
__device__ int g_ovf_cnt;
__device__ int g_ovf[OVF_MAX];

__device__ __forceinline__ ull pack2(float v) {
    ull d;
    asm("mov.b64 %0, {%1, %1};" : "=l"(d) : "f"(v));
    return d;
}
__device__ __forceinline__ ull fma2(ull a, ull b, ull c) {
    ull d;
    asm("fma.rn.f32x2 %0, %1, %2, %3;" : "=l"(d) : "l"(a), "l"(b), "l"(c));
    return d;
}
__device__ __forceinline__ float lo32(ull a) { return __uint_as_float((unsigned)a); }
__device__ __forceinline__ float hi32(ull a) { return __uint_as_float((unsigned)(a >> 32)); }

// ---------------------------------------------------------------------------
// Fused GEMM + CSR build (concatenated roles, as in the 81.8us baseline).
//   blockIdx.x <  gemmBlocks : 64-row GEMM tile, 256 threads
//   blockIdx.x >= gemmBlocks : 256 edges -> CSR slots
// ---------------------------------------------------------------------------
__global__ __launch_bounds__(256) void fused_gemm_build(
    const float* __restrict__ x, const float* __restrict__ W,
    float* __restrict__ y, int N,
    const int* __restrict__ ei, int E, int gemmBlocks)
{
    const int tid = threadIdx.x;

    if (blockIdx.x >= gemmBlocks) {
        // ----- CSR build branch -----
        int e = (blockIdx.x - gemmBlocks) * 256 + tid;
        if (e >= E) return;
        int src = __ldg(&ei[e]);
        int dst = __ldg(&ei[E + e]);
        if (((unsigned)src >= (unsigned)N) | ((unsigned)dst >= (unsigned)N)) return;
        int pos = atomicAdd(&g_deg[dst], 1);
        if (pos < CAP) {
            g_adj[(size_t)dst * CAP + pos] = src;
        } else {
            int i = atomicAdd(&g_ovf_cnt, 1);
            if (i < OVF_MAX) g_ovf[i] = e;
        }
        return;
    }

    // ----- GEMM branch: y = x @ W^T -----
    __shared__ float sWt[D][D + 4];   // sWt[k][o] = W[o][k]; row stride 272B (8B-aligned)
    __shared__ float sx[64][D];

    #pragma unroll
    for (int i = tid; i < D * D; i += 256)
        sWt[i & 63][i >> 6] = W[i];

    const int row0 = blockIdx.x * 64;
    #pragma unroll
    for (int it = 0; it < 4; it++) {
        int j = tid + it * 256;          // 0..1023 float4 slots
        int r = j >> 4, c4 = j & 15;
        int row = row0 + r;
        float4 v = make_float4(0.f, 0.f, 0.f, 0.f);
        if (row < N) v = reinterpret_cast<const float4*>(x)[(size_t)row * 16 + c4];
        reinterpret_cast<float4*>(&sx[r][0])[c4] = v;
    }
    __syncthreads();

    const int tx = tid & 15;
    const int ty = tid >> 4;

    // Accumulators: rows {ty, ty+16, ty+32, ty+48} x col-pairs {tx*4, tx*4+2}
    ull a0p = 0, a0q = 0, a1p = 0, a1q = 0;
    ull a2p = 0, a2q = 0, a3p = 0, a3q = 0;

    #pragma unroll 8
    for (int k = 0; k < D; k++) {
        // W col-pairs: adjacent floats -> direct LDS.64, already packed
        const ull* wrow = reinterpret_cast<const ull*>(&sWt[k][tx * 4]);
        ull wp = wrow[0];                 // cols (tx*4, tx*4+1)
        ull wq = wrow[1];                 // cols (tx*4+2, tx*4+3)
        ull x0 = pack2(sx[ty      ][k]);
        ull x1 = pack2(sx[ty + 16][k]);
        ull x2 = pack2(sx[ty + 32][k]);
        ull x3 = pack2(sx[ty + 48][k]);
        a0p = fma2(x0, wp, a0p); a0q = fma2(x0, wq, a0q);
        a1p = fma2(x1, wp, a1p); a1q = fma2(x1, wq, a1q);
        a2p = fma2(x2, wp, a2p); a2q = fma2(x2, wq, a2q);
        a3p = fma2(x3, wp, a3p); a3q = fma2(x3, wq, a3q);
    }

    float4* y4 = reinterpret_cast<float4*>(y);
    int r0 = row0 + ty;
    if (r0 < N)
        y4[(size_t)r0 * 16 + tx] = make_float4(lo32(a0p), hi32(a0p), lo32(a0q), hi32(a0q));
    if (r0 + 16 < N)
        y4[(size_t)(r0 + 16) * 16 + tx] = make_float4(lo32(a1p), hi32(a1p), lo32(a1q), hi32(a1q));
    if (r0 + 32 < N)
        y4[(size_t)(r0 + 32) * 16 + tx] = make_float4(lo32(a2p), hi32(a2p), lo32(a2q), hi32(a2q));
    if (r0 + 48 < N)
        y4[(size_t)(r0 + 48) * 16 + tx] = make_float4(lo32(a3p), hi32(a3p), lo32(a3q), hi32(a3q));
}

// ---------------------------------------------------------------------------
// Gather: 16 threads per dst (thread c owns float4 chunk c). Single write per
// output row, bias folded in, no atomics. Overflow fixup folded in.
// ---------------------------------------------------------------------------
__global__ __launch_bounds__(256) void gather_csr(
    const float* __restrict__ bias, float* __restrict__ out, int N,
    const int* __restrict__ ei, int E)
{
    int d = blockIdx.x * 16 + (threadIdx.x >> 4);
    int c = threadIdx.x & 15;
    if (d >= N) return;

    int cnt = g_deg[d];
    if (cnt > CAP) cnt = CAP;

    float4 acc = __ldg(reinterpret_cast<const float4*>(bias) + c);
    const int* lst = &g_adj[(size_t)d * CAP];
    const float4* y4 = reinterpret_cast<const float4*>(g_y);

    float4 acc2 = make_float4(0.f, 0.f, 0.f, 0.f);
    int i = 0;
    for (; i + 2 <= cnt; i += 2) {
        int s0 = __ldg(&lst[i]);
        int s1 = __ldg(&lst[i + 1]);
        float4 v0 = __ldg(y4 + (size_t)s0 * 16 + c);
        float4 v1 = __ldg(y4 + (size_t)s1 * 16 + c);
        acc.x  += v0.x; acc.y  += v0.y; acc.z  += v0.z; acc.w  += v0.w;
        acc2.x += v1.x; acc2.y += v1.y; acc2.z += v1.z; acc2.w += v1.w;
    }
    if (i < cnt) {
        int s0 = __ldg(&lst[i]);
        float4 v0 = __ldg(y4 + (size_t)s0 * 16 + c);
        acc.x += v0.x; acc.y += v0.y; acc.z += v0.z; acc.w += v0.w;
    }
    acc.x += acc2.x; acc.y += acc2.y; acc.z += acc2.z; acc.w += acc2.w;

    // Overflow fixup (statistically dead for Poisson(16) degrees, CAP=64)
    int ovf = g_ovf_cnt;
    if (ovf > 0) {
        if (ovf > OVF_MAX) ovf = OVF_MAX;
        for (int j = 0; j < ovf; j++) {
            int e = g_ovf[j];
            if (__ldg(&ei[E + e]) != d) continue;
            int s = __ldg(&ei[e]);
            float4 v = __ldg(y4 + (size_t)s * 16 + c);
            acc.x += v.x; acc.y += v.y; acc.z += v.z; acc.w += v.w;
        }
    }

    reinterpret_cast<float4*>(out)[(size_t)d * 16 + c] = acc;
}

// ---------------------------------------------------------------------------
extern "C" void kernel_launch(void* const* d_in, const int* in_sizes, int n_in,
                              void* d_out, int out_size)
{
    const float* x    = (const float*)d_in[0];
    const float* W    = (const float*)d_in[1];
    const float* bias = (const float*)d_in[2];
    const int*   ei   = (const int*)d_in[3];

    const int N = in_sizes[0] / D;
    const int E = in_sizes[3] / 2;
    float* out = (float*)d_out;

    float* y;     cudaGetSymbolAddress((void**)&y, g_y);
    void* degp;   cudaGetSymbolAddress(&degp, g_deg);
    void* ovfp;   cudaGetSymbolAddress(&ovfp, g_ovf_cnt);

    // 1) reset counters (graph-capturable memset nodes)
    cudaMemsetAsync(degp, 0, (size_t)N * sizeof(int));
    cudaMemsetAsync(ovfp, 0, sizeof(int));

    // 2) fused GEMM + CSR build (concatenated roles)
    const int gemmBlocks  = (N + 63) / 64;
    const int buildBlocks = (E + 255) / 256;
    fused_gemm_build<<<gemmBlocks + buildBlocks, 256>>>(x, W, y, N, ei, E, gemmBlocks);

    // 3) dst-centric accumulate (+bias, +overflow fixup)
    gather_csr<<<(N + 15) / 16, 256>>>(bias, out, N, ei, E);
}